// round 7
// baseline (speedup 1.0000x reference)
#include <cuda_runtime.h>
#include <cuda_fp16.h>
#include <cstdint>

#define TWO_N 8192
#define NHALF 4096
#define DDIM  256
#define BM 128
#define NBLK 2080            // 64*65/2 upper-triangle 128x128 blocks
#define NCTA 148
#define NTHR 256             // 8 warps: 4(M) x 2(N), warp tile 32x64
#define CHUNK_BYTES 16384    // one [128 rows][128B] swizzled k-chunk
#define TILE_BYTES  65536    // 128 x 256 fp16

__device__ __half g_znh[TWO_N * DDIM];
__device__ float g_pr[(size_t)NBLK * 128];  // per-block row partial sums
__device__ float g_pc[(size_t)NBLK * 128];  // per-block col partial sums
__device__ float g_bs[64];                  // per-rowblock loss partial
__device__ int   g_cnt;                     // last-block counter

#define L2E2 2.8853900817779268f    /* 2/ln2 : exp(2d) = 2^(d*L2E2) */

// ---------------------------------------------------------------- helpers --
__device__ __forceinline__ uint32_t smem_u32(const void* p) {
    uint32_t a;
    asm("{ .reg .u64 t; cvta.to.shared.u64 t, %1; cvt.u32.u64 %0, t; }"
        : "=r"(a) : "l"(p));
    return a;
}
__device__ __forceinline__ float ex2f(float x) {
    float y; asm("ex2.approx.f32 %0, %1;" : "=f"(y) : "f"(x)); return y;
}
#define CP_ASYNC16(sm, gp) \
    asm volatile("cp.async.cg.shared.global [%0], [%1], 16;" \
                 :: "r"(sm), "l"(gp) : "memory")
#define CP_COMMIT()  asm volatile("cp.async.commit_group;" ::: "memory")
#define CP_WAIT(n)   asm volatile("cp.async.wait_group %0;" :: "n"(n) : "memory")

__device__ __forceinline__ void ldsm_x4(uint32_t* r, uint32_t addr) {
    asm volatile("ldmatrix.sync.aligned.m8n8.x4.shared.b16 {%0,%1,%2,%3}, [%4];"
                 : "=r"(r[0]), "=r"(r[1]), "=r"(r[2]), "=r"(r[3]) : "r"(addr));
}
// fp16 accumulate: D,C are 2 regs (4 halves)
__device__ __forceinline__ void mma16816h(uint32_t* c, const uint32_t* a,
                                          uint32_t b0, uint32_t b1) {
    asm volatile(
        "mma.sync.aligned.m16n8k16.row.col.f16.f16.f16.f16 "
        "{%0,%1}, {%2,%3,%4,%5}, {%6,%7}, {%0,%1};"
        : "+r"(c[0]), "+r"(c[1])
        : "r"(a[0]), "r"(a[1]), "r"(a[2]), "r"(a[3]), "r"(b0), "r"(b1));
}

// upper-triangle block id in paired-strip order
__device__ __forceinline__ int bidx(int I, int J) {   // I <= J
    return (I < 32) ? (64 * I + J) : (65 * (63 - I) + I + 1 + (J - I));
}
__device__ __forceinline__ void bdecode(int g, int& I, int& J) {
    int p = g / 65, r = g - p * 65;
    if (r < 64 - p) { I = p;      J = p + r; }
    else            { I = 63 - p; J = I + (r - (64 - p)); }
}

// ---------------------------------------------------------------------------
// Kernel 1: L2-normalize rows -> fp16. One warp per row, no smem.
// ---------------------------------------------------------------------------
__global__ void norm_kernel(const float* __restrict__ z1,
                            const float* __restrict__ z2) {
    int wid = threadIdx.x >> 5, lane = threadIdx.x & 31;
    int row = blockIdx.x * 8 + wid;
    const float4* src = reinterpret_cast<const float4*>(
        (row < NHALF) ? (z1 + (size_t)row * DDIM)
                      : (z2 + (size_t)(row - NHALF) * DDIM));
    float4 v0 = src[lane];
    float4 v1 = src[lane + 32];
    float ss = v0.x * v0.x + v0.y * v0.y + v0.z * v0.z + v0.w * v0.w
             + v1.x * v1.x + v1.y * v1.y + v1.z * v1.z + v1.w * v1.w;
#pragma unroll
    for (int o = 16; o; o >>= 1) ss += __shfl_xor_sync(0xffffffffu, ss, o);
    float inv = 1.0f / fmaxf(sqrtf(ss), 1e-8f);
    __half2 a0 = __floats2half2_rn(v0.x * inv, v0.y * inv);
    __half2 a1 = __floats2half2_rn(v0.z * inv, v0.w * inv);
    __half2 b0 = __floats2half2_rn(v1.x * inv, v1.y * inv);
    __half2 b1 = __floats2half2_rn(v1.z * inv, v1.w * inv);
    uint2* dst = reinterpret_cast<uint2*>(g_znh + (size_t)row * DDIM);
    dst[lane]      = make_uint2(*(uint32_t*)&a0, *(uint32_t*)&a1);
    dst[lane + 32] = make_uint2(*(uint32_t*)&b0, *(uint32_t*)&b1);
}

// ---------------------------------------------------------------------------
// tile loader: 128 rows x 256 fp16 -> swizzled k-chunks via cp.async
// ---------------------------------------------------------------------------
__device__ __forceinline__ void load_tile(uint32_t sdst, int rowblk, int tid) {
    const char* gsrc = (const char*)(g_znh + (size_t)rowblk * BM * DDIM);
#pragma unroll
    for (int i = 0; i < 16; i++) {
        int unit = i * NTHR + tid;           // row*32 + uu
        int row = unit >> 5, uu = unit & 31;
        uint32_t off = (uint32_t)(row * 128 + (uu & 7) * 16);
        off ^= (off >> 3) & 0x70;
        CP_ASYNC16(sdst + (uu >> 3) * CHUNK_BYTES + off, gsrc + unit * 16);
    }
}

// ---------------------------------------------------------------------------
// Kernel 2: symmetric fp16-accum HMMA GEMM, deferred epilogue.
// grid = 148 persistent CTAs over 2080 blocks in paired-strip order.
// ---------------------------------------------------------------------------
__global__ void __launch_bounds__(NTHR, 1) sim_kernel() {
    extern __shared__ char smem_raw[];
    char* sbase = (char*)(((uintptr_t)smem_raw + 1023) & ~(uintptr_t)1023);
    uint32_t sAu = smem_u32(sbase);              // A: 64 KB (single)
    uint32_t sBu = sAu + TILE_BYTES;             // B: 2 x 64 KB

    __shared__ float s_rs[2][BM];                // n-half rowsum partials
    __shared__ float s_cs[8][64];                // [mwarp*2+nhalf][col]

    int tid = threadIdx.x;
    int wid = tid >> 5, lane = tid & 31;
    int cta = blockIdx.x;
    int start = cta * 14 + (cta < 8 ? cta : 8);
    int cnt = 14 + (cta < 8 ? 1 : 0);

    int m_base = (wid >> 1) * 32;
    int n_base = (wid & 1) * 64;
    int mwarp = wid >> 1, nhalf = wid & 1;

    // ---- per-lane ldmatrix address pieces ----
    int rA0 = m_base + (lane & 15);
    int rA1 = rA0 + 16;
    uint32_t kaddA = ((lane >> 4) & 1) * 16;
    uint32_t rowA0 = (uint32_t)rA0 * 128, xA0 = (uint32_t)(rA0 & 7) << 4;
    uint32_t rowA1 = (uint32_t)rA1 * 128, xA1 = (uint32_t)(rA1 & 7) << 4;
    int rBb = n_base + (lane & 7) + ((lane & 16) >> 1);
    uint32_t kaddB = ((lane >> 3) & 1) * 16;
    uint32_t rowB[4], xB[4];
#pragma unroll
    for (int gI = 0; gI < 4; gI++) {
        int r = rBb + gI * 16;
        rowB[gI] = (uint32_t)r * 128;
        xB[gI] = (uint32_t)(r & 7) << 4;
    }
    int lrow[4];
#pragma unroll
    for (int s = 0; s < 4; s++)
        lrow[s] = m_base + (s >> 1) * 16 + (lane >> 2) + (s & 1) * 8;

    uint32_t accA[2][8][2], accB[2][8][2];       // fp16x2 accumulators
    float rs[4] = {0.f, 0.f, 0.f, 0.f};
    float cs[8][2];
#pragma unroll
    for (int j = 0; j < 8; j++) { cs[j][0] = 0.f; cs[j][1] = 0.f; }
    int curI;

    auto flush_old = [&](int oI, int oJ, int oblk) {
#pragma unroll
        for (int s2 = 0; s2 < 4; s2++) {
            float v = rs[s2];
            v += __shfl_xor_sync(0xffffffffu, v, 1);
            v += __shfl_xor_sync(0xffffffffu, v, 2);
            if ((lane & 3) == 0) s_rs[nhalf][lrow[s2]] = v;
        }
        if (oI != oJ) {
#pragma unroll
            for (int j = 0; j < 8; j++)
#pragma unroll
                for (int cb = 0; cb < 2; cb++) {
                    float v = cs[j][cb];
                    v += __shfl_xor_sync(0xffffffffu, v, 4);
                    v += __shfl_xor_sync(0xffffffffu, v, 8);
                    v += __shfl_xor_sync(0xffffffffu, v, 16);
                    if (lane < 4)
                        s_cs[mwarp * 2 + nhalf][j * 8 + lane * 2 + cb] = v;
                }
        }
        __syncthreads();
        if (tid < BM) {
            size_t boff = (size_t)oblk * 128 + tid;
            g_pr[boff] = s_rs[0][tid] + s_rs[1][tid];
            if (oI != oJ) {
                int nh = tid >> 6, cc = tid & 63;
                g_pc[boff] = s_cs[nh][cc] + s_cs[2 + nh][cc] +
                             s_cs[4 + nh][cc] + s_cs[6 + nh][cc];
            }
        }
#pragma unroll
        for (int s2 = 0; s2 < 4; s2++) rs[s2] = 0.f;
#pragma unroll
        for (int j = 0; j < 8; j++) { cs[j][0] = 0.f; cs[j][1] = 0.f; }
    };

    auto run_block = [&](uint32_t (&acc)[2][8][2], uint32_t (&aold)[2][8][2],
                         int n, int oI, int oJ, bool do_old) {
        if (n + 1 < cnt) {
            int In, Jn; bdecode(start + n + 1, In, Jn);
            load_tile(sBu + ((n + 1) & 1) * TILE_BYTES, Jn, tid);
            CP_COMMIT();
            CP_WAIT(1);
        } else {
            CP_WAIT(0);
        }
        __syncthreads();

#pragma unroll
        for (int i = 0; i < 2; i++)
#pragma unroll
            for (int j = 0; j < 8; j++) { acc[i][j][0] = 0u; acc[i][j][1] = 0u; }

        uint32_t bbase = sBu + (n & 1) * TILE_BYTES;

#pragma unroll
        for (int s = 0; s < 16; s++) {           // k = s*16
            uint32_t coff = (uint32_t)(s >> 2) * CHUNK_BYTES;
            uint32_t kbA = (uint32_t)(s & 3) * 32 + kaddA;
            uint32_t kbB = (uint32_t)(s & 3) * 32 + kaddB;
            uint32_t a0[4], a1[4], b[4][4];
            ldsm_x4(a0, sAu + coff + rowA0 + (kbA ^ xA0));
            ldsm_x4(a1, sAu + coff + rowA1 + (kbA ^ xA1));
#pragma unroll
            for (int gI = 0; gI < 4; gI++)
                ldsm_x4(b[gI], bbase + coff + rowB[gI] + (kbB ^ xB[gI]));

            // deferred epilogue chunk: reg-pair (ii, jj) of old block
            if (do_old) {
                const int ii = s >> 3, jj = s & 7;
#pragma unroll
                for (int g = 0; g < 2; g++) {
                    float2 f = __half22float2(
                        *reinterpret_cast<__half2*>(&aold[ii][jj][g]));
                    float e0 = ex2f(f.x * L2E2);
                    float e1 = ex2f(f.y * L2E2);
                    rs[ii * 2 + g] += e0 + e1;
                    cs[jj][0] += e0;
                    cs[jj][1] += e1;
                }
            }

#pragma unroll
            for (int j = 0; j < 8; j++) {
                uint32_t b0 = b[j >> 1][(j & 1) * 2];
                uint32_t b1 = b[j >> 1][(j & 1) * 2 + 1];
                mma16816h(acc[0][j], a0, b0, b1);
                mma16816h(acc[1][j], a1, b0, b1);
            }
        }
        __syncthreads();   // sA / sB[n&1] no longer read

        if (n + 1 < cnt) {
            int In, Jn; bdecode(start + n + 1, In, Jn);
            if (In != curI) { load_tile(sAu, In, tid); CP_COMMIT(); curI = In; }
        }
        if (do_old) flush_old(oI, oJ, start + n - 1);
    };

    // ---- prologue ----
    int I0, J0; bdecode(start, I0, J0);
    load_tile(sAu, I0, tid); CP_COMMIT();
    load_tile(sBu, J0, tid); CP_COMMIT();
    curI = I0;

    bool useA = true;
    int pI = 0, pJ = 0;
#pragma unroll 1
    for (int n = 0; n < cnt; n++) {
        int I, J; bdecode(start + n, I, J);
        if (useA) run_block(accA, accB, n, pI, pJ, n > 0);
        else      run_block(accB, accA, n, pI, pJ, n > 0);
        useA = !useA; pI = I; pJ = J;
    }

    // ---- final (non-interleaved) epilogue for the last block ----
    {
        __syncthreads();
#pragma unroll
        for (int ii = 0; ii < 2; ii++)
#pragma unroll
            for (int jj = 0; jj < 8; jj++)
#pragma unroll
                for (int g = 0; g < 2; g++) {
                    uint32_t raw = useA ? accB[ii][jj][g] : accA[ii][jj][g];
                    float2 f = __half22float2(*reinterpret_cast<__half2*>(&raw));
                    float e0 = ex2f(f.x * L2E2);
                    float e1 = ex2f(f.y * L2E2);
                    rs[ii * 2 + g] += e0 + e1;
                    cs[jj][0] += e0;
                    cs[jj][1] += e1;
                }
        flush_old(pI, pJ, start + cnt - 1);
    }
}

// ---------------------------------------------------------------------------
// Kernel 3: per-row combine; exact fp32 self/pos dots; last block -> mean.
// ---------------------------------------------------------------------------
__global__ void reduce_kernel(float* __restrict__ out) {
    int R = blockIdx.x, q = threadIdx.x;     // 64 blocks x 128 threads
    int r = R * 128 + q;
    int p = r ^ NHALF;                       // positive-pair row

    // exact fp32 self & pair dots from the fp16 rows
    const __half2* va = reinterpret_cast<const __half2*>(g_znh + (size_t)r * DDIM);
    const __half2* vb = reinterpret_cast<const __half2*>(g_znh + (size_t)p * DDIM);
    float dd = 0.f, pd = 0.f;
#pragma unroll 8
    for (int i = 0; i < DDIM / 2; i++) {
        float2 fa = __half22float2(va[i]);
        float2 fb = __half22float2(vb[i]);
        dd += fa.x * fa.x + fa.y * fa.y;
        pd += fa.x * fb.x + fa.y * fb.y;
    }

    float tot = 0.f;
#pragma unroll 4
    for (int J = R; J < 64; J++) tot += g_pr[(size_t)bidx(R, J) * 128 + q];
#pragma unroll 4
    for (int I = 0; I < R; I++)  tot += g_pc[(size_t)bidx(I, R) * 128 + q];
    tot -= ex2f(dd * L2E2);                  // remove self term
    float lv = logf(tot) - 2.0f * pd;

    int lane = q & 31;
#pragma unroll
    for (int o = 16; o; o >>= 1) lv += __shfl_xor_sync(0xffffffffu, lv, o);
    __shared__ float w[4];
    __shared__ int slast;
    __shared__ float aa[2];
    if (lane == 0) w[q >> 5] = lv;
    __syncthreads();
    if (q == 0) {
        g_bs[R] = w[0] + w[1] + w[2] + w[3];
        __threadfence();
        slast = (atomicAdd(&g_cnt, 1) == 63);
    }
    __syncthreads();
    if (slast) {
        __threadfence();
        if (q < 64) {
            float v = g_bs[q];
#pragma unroll
            for (int o = 16; o; o >>= 1) v += __shfl_xor_sync(0xffffffffu, v, o);
            if ((q & 31) == 0) aa[q >> 5] = v;
        }
        __syncthreads();
        if (q == 0) {
            out[0] = (aa[0] + aa[1]) / (float)TWO_N;
            g_cnt = 0;                       // reset for graph replay
        }
    }
}

// ---------------------------------------------------------------------------
extern "C" void kernel_launch(void* const* d_in, const int* in_sizes, int n_in,
                              void* d_out, int out_size) {
    const float* z1 = (const float*)d_in[0];
    const float* z2 = (const float*)d_in[1];
    float* out = (float*)d_out;

    norm_kernel<<<TWO_N / 8, 256>>>(z1, z2);

    size_t smem = 3 * TILE_BYTES + 1024;   // 197,632 B
    cudaFuncSetAttribute(sim_kernel, cudaFuncAttributeMaxDynamicSharedMemorySize,
                         (int)smem);
    sim_kernel<<<NCTA, NTHR, smem>>>();

    reduce_kernel<<<64, 128>>>(out);
}